// round 1
// baseline (speedup 1.0000x reference)
#include <cuda_runtime.h>
#include <cstdint>

// Problem constants
static constexpr int NB = 16;    // batch
static constexpr int NC = 256;   // channels
static constexpr int NH = 64;
static constexpr int NW = 64;
static constexpr int NP = 9;     // patch (2*4+1)
static constexpr int DISP = 4;

// Tiling
static constexpr int TI = 4;             // i-rows per block
static constexpr int CH = 4;             // channels per pipeline stage
static constexpr int NSTAGE = NC / CH;   // 64
static constexpr int YROWS = TI + 2 * DISP;  // 12
static constexpr int PITCH = 384;        // bytes per smem row (multiple of 128)
static constexpr int XAREA = CH * TI * PITCH;      // 6144
static constexpr int YAREA = CH * YROWS * PITCH;   // 18432
static constexpr int BUFBYTES = XAREA + YAREA;     // 24576
static constexpr int NTHREADS = 288;     // 9 warps: warp w -> di = w

// Per-row skew so that 8-lane LDS.128 phases hit 8 distinct 16B bank groups.
// SKEW(r%4) in {0,16,64,80} bytes; combined with jg*32 + k*16 this is a perfect
// permutation of the 8 x 16B slots in a 128B window.
__device__ __forceinline__ unsigned skew(int r) {
    return ((r & 1) << 4) + ((r & 2) << 5);
}

__device__ __forceinline__ unsigned long long pk(float lo, float hi) {
    unsigned long long r;
    asm("mov.b64 %0, {%1, %2};" : "=l"(r) : "f"(lo), "f"(hi));
    return r;
}
__device__ __forceinline__ void upk(unsigned long long v, float& lo, float& hi) {
    asm("mov.b64 {%0, %1}, %2;" : "=f"(lo), "=f"(hi) : "l"(v));
}
// Packed dual fp32 FMA (Blackwell): 2x FFMA throughput vs scalar FFMA.
__device__ __forceinline__ void fma2(unsigned long long& acc,
                                     unsigned long long a, unsigned long long b) {
    asm("fma.rn.f32x2 %0, %1, %2, %0;" : "+l"(acc) : "l"(a), "l"(b));
}
__device__ __forceinline__ void cpa16(unsigned dst, const void* src) {
    asm volatile("cp.async.cg.shared.global [%0], [%1], 16;"
                 :: "r"(dst), "l"(src) : "memory");
}

__global__ void __launch_bounds__(NTHREADS)
corr_kernel(const float* __restrict__ x, const float* __restrict__ y,
            float* __restrict__ out) {
    extern __shared__ char smem[];

    const int tid = threadIdx.x;
    const int di  = tid >> 5;        // 0..8, one displacement-row per warp
    const int lane = tid & 31;
    const int jg  = lane >> 2;       // 0..7 : group of 8 output columns
    const int ti  = lane & 3;        // 0..3 : i-row inside tile
    const int i0  = blockIdx.x * TI;
    const int b   = blockIdx.y;

    unsigned smem_u32;
    asm("{ .reg .u64 t; cvta.to.shared.u64 t, %1; cvt.u32.u64 %0, t; }"
        : "=r"(smem_u32) : "l"(smem));

    // Zero both buffers once: halo columns / out-of-range rows stay zero forever.
    for (int o = tid * 16; o < 2 * BUFBYTES; o += NTHREADS * 16)
        *reinterpret_cast<float4*>(smem + o) = make_float4(0.f, 0.f, 0.f, 0.f);
    __syncthreads();

    unsigned long long acc[NP][4];
#pragma unroll
    for (int d = 0; d < NP; ++d)
#pragma unroll
        for (int m = 0; m < 4; ++m) acc[d][m] = 0ull;

    const int r = ti + di;  // y smem row for this thread (0..11)
    const unsigned xoff = (unsigned)(ti * PITCH) + skew(ti) + jg * 32;
    const unsigned yoff = (unsigned)XAREA + (unsigned)(r * PITCH) + skew(r) + jg * 32;

    // ---- async stage loader ----
    auto issue = [&](int stage) {
        const int c0 = stage * CH;
        const unsigned sb = smem_u32 + (unsigned)((stage & 1) * BUFBYTES);
        const int NYI = CH * YROWS * 16;                 // 768 y transfers
        const int NTOT = NYI + CH * TI * 16;             // + 256 x transfers
        for (int idx = tid; idx < NTOT; idx += NTHREADS) {
            if (idx < NYI) {
                const int cc = idx / (YROWS * 16);
                const int rr = (idx >> 4) % YROWS;
                const int q  = idx & 15;
                const int gy = i0 - DISP + rr;
                if ((unsigned)gy < (unsigned)NH) {
                    const float* src =
                        y + (((size_t)(b * NC + c0 + cc) * NH + gy) * NW + q * 4);
                    const unsigned dst = sb + XAREA + (unsigned)(cc * (YROWS * PITCH))
                                         + (unsigned)(rr * PITCH) + skew(rr)
                                         + 16u + (unsigned)(q * 16);
                    cpa16(dst, src);
                }
            } else {
                const int j  = idx - NYI;
                const int cc = j / (TI * 16);
                const int rr = (j >> 4) % TI;
                const int q  = j & 15;
                const float* src =
                    x + (((size_t)(b * NC + c0 + cc) * NH + (i0 + rr)) * NW + q * 4);
                const unsigned dst = sb + (unsigned)(cc * (TI * PITCH))
                                     + (unsigned)(rr * PITCH) + skew(rr)
                                     + (unsigned)(q * 16);
                cpa16(dst, src);
            }
        }
        asm volatile("cp.async.commit_group;" ::: "memory");
    };

    issue(0);

    for (int s = 0; s < NSTAGE; ++s) {
        if (s + 1 < NSTAGE) {
            issue(s + 1);
            asm volatile("cp.async.wait_group 1;" ::: "memory");
        } else {
            asm volatile("cp.async.wait_group 0;" ::: "memory");
        }
        __syncthreads();

        const char* base = smem + (s & 1) * BUFBYTES;
#pragma unroll
        for (int cc = 0; cc < CH; ++cc) {
            const char* xp = base + cc * (TI * PITCH) + xoff;
            const char* yp = base + cc * (YROWS * PITCH) + yoff;

            const float4 xa = *reinterpret_cast<const float4*>(xp);
            const float4 xb = *reinterpret_cast<const float4*>(xp + 16);
            const float4 y0 = *reinterpret_cast<const float4*>(yp);
            const float4 y1 = *reinterpret_cast<const float4*>(yp + 16);
            const float4 y2 = *reinterpret_cast<const float4*>(yp + 32);
            const float4 y3 = *reinterpret_cast<const float4*>(yp + 48);

            unsigned long long X[4] = {pk(xa.x, xa.y), pk(xa.z, xa.w),
                                       pk(xb.x, xb.y), pk(xb.z, xb.w)};
            const float w[16] = {y0.x, y0.y, y0.z, y0.w, y1.x, y1.y, y1.z, y1.w,
                                 y2.x, y2.y, y2.z, y2.w, y3.x, y3.y, y3.z, y3.w};

            unsigned long long Wp[8], Sp[7];
#pragma unroll
            for (int q = 0; q < 8; ++q) Wp[q] = pk(w[2 * q], w[2 * q + 1]);
#pragma unroll
            for (int q = 0; q < 7; ++q) Sp[q] = pk(w[2 * q + 1], w[2 * q + 2]);

#pragma unroll
            for (int dj = 0; dj < NP; ++dj) {
                const int e = dj >> 1;
#pragma unroll
                for (int m = 0; m < 4; ++m) {
                    const unsigned long long yv = (dj & 1) ? Sp[m + e] : Wp[m + e];
                    fma2(acc[dj][m], X[m], yv);
                }
            }
        }
        __syncthreads();
    }

    // ---- epilogue: scale by 1/C and store ----
    const float sc = 1.0f / (float)NC;
    float* obase = out + (((size_t)b * (NP * NP) + (size_t)di * NP) * NH + (i0 + ti)) * NW
                       + jg * 8;
#pragma unroll
    for (int dj = 0; dj < NP; ++dj) {
        float4 o;
        upk(acc[dj][0], o.x, o.y);
        upk(acc[dj][1], o.z, o.w);
        o.x *= sc; o.y *= sc; o.z *= sc; o.w *= sc;
        *reinterpret_cast<float4*>(obase + (size_t)dj * NH * NW) = o;
        upk(acc[dj][2], o.x, o.y);
        upk(acc[dj][3], o.z, o.w);
        o.x *= sc; o.y *= sc; o.z *= sc; o.w *= sc;
        *reinterpret_cast<float4*>(obase + (size_t)dj * NH * NW + 4) = o;
    }
}

extern "C" void kernel_launch(void* const* d_in, const int* in_sizes, int n_in,
                              void* d_out, int out_size) {
    const float* x = (const float*)d_in[0];
    const float* y = (const float*)d_in[1];
    float* out = (float*)d_out;
    (void)in_sizes; (void)n_in; (void)out_size;

    dim3 grid(NH / TI, NB);   // (16, 16) = 256 blocks
    corr_kernel<<<grid, NTHREADS, 2 * BUFBYTES>>>(x, y, out);
}

// round 2
// speedup vs baseline: 1.5447x; 1.5447x over previous
#include <cuda_runtime.h>
#include <cstdint>

// Problem constants
static constexpr int NB = 16;    // batch
static constexpr int NC = 256;   // channels
static constexpr int NH = 64;
static constexpr int NW = 64;
static constexpr int NP = 9;     // patch (2*4+1)
static constexpr int DISP = 4;

// Tiling
static constexpr int TI = 4;             // i-rows per block
static constexpr int CH = 4;             // channels per pipeline stage
static constexpr int NSTAGE = NC / CH;   // 64
static constexpr int YROWS = TI + 2 * DISP;  // 12
static constexpr int PITCH = 384;        // bytes per smem row (multiple of 128)
static constexpr int XAREA = CH * TI * PITCH;      // 6144
static constexpr int YAREA = CH * YROWS * PITCH;   // 18432
static constexpr int BUFBYTES = XAREA + YAREA;     // 24576
static constexpr int NTHREADS = 288;     // 9 warps: warp w -> di = w
static constexpr int NXFER = CH * YROWS * 16 + CH * TI * 16;  // 768 + 256 = 1024
static constexpr int NYI = CH * YROWS * 16;                   // 768
static constexpr int STAGE_BYTES = CH * NH * NW * 4;          // 65536

__device__ __forceinline__ unsigned skew(int r) {
    return ((r & 1) << 4) + ((r & 2) << 5);
}

__device__ __forceinline__ unsigned long long pk(float lo, float hi) {
    unsigned long long r;
    asm("mov.b64 %0, {%1, %2};" : "=l"(r) : "f"(lo), "f"(hi));
    return r;
}
__device__ __forceinline__ void upk(unsigned long long v, float& lo, float& hi) {
    asm("mov.b64 {%0, %1}, %2;" : "=f"(lo), "=f"(hi) : "l"(v));
}
// Packed dual fp32 FMA (Blackwell): 2x FFMA throughput vs scalar FFMA.
__device__ __forceinline__ void fma2(unsigned long long& acc,
                                     unsigned long long a, unsigned long long b) {
    asm("fma.rn.f32x2 %0, %1, %2, %0;" : "+l"(acc) : "l"(a), "l"(b));
}
__device__ __forceinline__ void cpa16(unsigned dst, const void* src) {
    asm volatile("cp.async.cg.shared.global [%0], [%1], 16;"
                 :: "r"(dst), "l"(src) : "memory");
}

__global__ void __launch_bounds__(NTHREADS, 2)
corr_kernel(const float* __restrict__ x, const float* __restrict__ y,
            float* __restrict__ out) {
    extern __shared__ char smem[];

    const int tid = threadIdx.x;
    const int di  = tid >> 5;        // 0..8, one displacement-row per warp
    const int lane = tid & 31;
    const int jg  = lane >> 2;       // 0..7 : group of 8 output columns
    const int ti  = lane & 3;        // 0..3 : i-row inside tile
    const int i0  = blockIdx.x * TI;
    const int b   = blockIdx.y;

    unsigned smem_u32;
    asm("{ .reg .u64 t; cvta.to.shared.u64 t, %1; cvt.u32.u64 %0, t; }"
        : "=r"(smem_u32) : "l"(smem));

    // Zero both buffers once: halo columns / out-of-range rows stay zero forever.
    for (int o = tid * 16; o < 2 * BUFBYTES; o += NTHREADS * 16)
        *reinterpret_cast<float4*>(smem + o) = make_float4(0.f, 0.f, 0.f, 0.f);

    // ---- precompute this thread's transfer slots (stage-invariant) ----
    // Slot k handles global transfer index tid + k*NTHREADS of the 1024 per stage.
    const char* sp[4];      // stage-0 source address
    int         doff[4];    // dest offset within buffer; -1 = skip
#pragma unroll
    for (int k = 0; k < 4; ++k) {
        const int idx = tid + k * NTHREADS;
        sp[k] = reinterpret_cast<const char*>(x);
        doff[k] = -1;
        if (idx < NYI) {
            const int cc = idx / (YROWS * 16);
            const int rr = (idx >> 4) % YROWS;
            const int q  = idx & 15;
            const int gy = i0 - DISP + rr;
            if ((unsigned)gy < (unsigned)NH) {
                sp[k] = reinterpret_cast<const char*>(
                    y + (((size_t)(b * NC + cc) * NH + gy) * NW + q * 4));
                doff[k] = XAREA + cc * (YROWS * PITCH) + rr * PITCH
                          + (int)skew(rr) + 16 + q * 16;
            }
        } else if (idx < NXFER) {
            const int j  = idx - NYI;
            const int cc = j / (TI * 16);
            const int rr = (j >> 4) & 3;
            const int q  = j & 15;
            sp[k] = reinterpret_cast<const char*>(
                x + (((size_t)(b * NC + cc) * NH + (i0 + rr)) * NW + q * 4));
            doff[k] = cc * (TI * PITCH) + rr * PITCH + (int)skew(rr) + q * 16;
        }
    }
    __syncthreads();

    unsigned long long acc[NP][4];
#pragma unroll
    for (int d = 0; d < NP; ++d)
#pragma unroll
        for (int m = 0; m < 4; ++m) acc[d][m] = 0ull;

    const int r = ti + di;  // y smem row for this thread (0..11)
    const unsigned xoff = (unsigned)(ti * PITCH) + skew(ti) + jg * 32;
    const unsigned yoff = (unsigned)XAREA + (unsigned)(r * PITCH) + skew(r) + jg * 32;

    // ---- cheap per-stage issue: pointer bump + fixed dst ----
    auto issue = [&](int stage) {
        const unsigned sb = smem_u32 + (unsigned)((stage & 1) * BUFBYTES);
        const int soff = stage * STAGE_BYTES;
#pragma unroll
        for (int k = 0; k < 4; ++k)
            if (doff[k] >= 0) cpa16(sb + (unsigned)doff[k], sp[k] + soff);
        asm volatile("cp.async.commit_group;" ::: "memory");
    };

    issue(0);

    for (int s = 0; s < NSTAGE; ++s) {
        if (s + 1 < NSTAGE) {
            issue(s + 1);
            asm volatile("cp.async.wait_group 1;" ::: "memory");
        } else {
            asm volatile("cp.async.wait_group 0;" ::: "memory");
        }
        __syncthreads();

        const char* base = smem + (s & 1) * BUFBYTES;
#pragma unroll
        for (int cc = 0; cc < CH; ++cc) {
            const char* xp = base + cc * (TI * PITCH) + xoff;
            const char* yp = base + cc * (YROWS * PITCH) + yoff;

            const float4 xa = *reinterpret_cast<const float4*>(xp);
            const float4 xb = *reinterpret_cast<const float4*>(xp + 16);
            const float4 y0 = *reinterpret_cast<const float4*>(yp);
            const float4 y1 = *reinterpret_cast<const float4*>(yp + 16);
            const float4 y2 = *reinterpret_cast<const float4*>(yp + 32);
            const float4 y3 = *reinterpret_cast<const float4*>(yp + 48);

            unsigned long long X[4] = {pk(xa.x, xa.y), pk(xa.z, xa.w),
                                       pk(xb.x, xb.y), pk(xb.z, xb.w)};
            const float w[16] = {y0.x, y0.y, y0.z, y0.w, y1.x, y1.y, y1.z, y1.w,
                                 y2.x, y2.y, y2.z, y2.w, y3.x, y3.y, y3.z, y3.w};

            unsigned long long Wp[8], Sp[7];
#pragma unroll
            for (int q = 0; q < 8; ++q) Wp[q] = pk(w[2 * q], w[2 * q + 1]);
#pragma unroll
            for (int q = 0; q < 7; ++q) Sp[q] = pk(w[2 * q + 1], w[2 * q + 2]);

#pragma unroll
            for (int dj = 0; dj < NP; ++dj) {
                const int e = dj >> 1;
#pragma unroll
                for (int m = 0; m < 4; ++m) {
                    const unsigned long long yv = (dj & 1) ? Sp[m + e] : Wp[m + e];
                    fma2(acc[dj][m], X[m], yv);
                }
            }
        }
        __syncthreads();
    }

    // ---- epilogue: scale by 1/C and store ----
    const float sc = 1.0f / (float)NC;
    float* obase = out + (((size_t)b * (NP * NP) + (size_t)di * NP) * NH + (i0 + ti)) * NW
                       + jg * 8;
#pragma unroll
    for (int dj = 0; dj < NP; ++dj) {
        float4 o;
        upk(acc[dj][0], o.x, o.y);
        upk(acc[dj][1], o.z, o.w);
        o.x *= sc; o.y *= sc; o.z *= sc; o.w *= sc;
        *reinterpret_cast<float4*>(obase + (size_t)dj * NH * NW) = o;
        upk(acc[dj][2], o.x, o.y);
        upk(acc[dj][3], o.z, o.w);
        o.x *= sc; o.y *= sc; o.z *= sc; o.w *= sc;
        *reinterpret_cast<float4*>(obase + (size_t)dj * NH * NW + 4) = o;
    }
}

extern "C" void kernel_launch(void* const* d_in, const int* in_sizes, int n_in,
                              void* d_out, int out_size) {
    const float* x = (const float*)d_in[0];
    const float* y = (const float*)d_in[1];
    float* out = (float*)d_out;
    (void)in_sizes; (void)n_in; (void)out_size;

    static bool attr_set = false;
    if (!attr_set) {
        cudaFuncSetAttribute(corr_kernel,
                             cudaFuncAttributeMaxDynamicSharedMemorySize,
                             2 * BUFBYTES);
        attr_set = true;
    }

    dim3 grid(NH / TI, NB);   // (16, 16) = 256 blocks
    corr_kernel<<<grid, NTHREADS, 2 * BUFBYTES>>>(x, y, out);
}